// round 13
// baseline (speedup 1.0000x reference)
#include <cuda_runtime.h>

// Trilinear resize [4,128,128,128,2] f32 -> [4,192,192,192,2] f32, zoom=1.5.
// Best skeleton (R3/R12) + float4 cooperative loads + plain stores.
//
// zoom=1.5 is exactly 3 outputs per 2 inputs with fixed weights {1, 1/3, 2/3}
// per axis (offset 0 is an exact copy). Block = (b, zk, yk): stages input
// strip [3z][3y][128x] in smem via coalesced float4 loads (explicit 3x3 row
// structure, no divides); thread = one output x column, x-lerp from smem,
// y/z lerps in registers, 27 perfectly coalesced STG.64 with compile-time
// immediate offsets.

#define IN_D  128
#define OUT_D 192

__device__ __forceinline__ float2 lerp2(float2 a, float2 b, float wa, float wb) {
    return make_float2(fmaf(a.x, wa, b.x * wb), fmaf(a.y, wa, b.y * wb));
}

__global__ __launch_bounds__(192) void resize_smem_f4_kernel(
    const float2* __restrict__ in,   // [4,128,128,128] voxels (C=2 packed)
    float2* __restrict__ out)        // [4,192,192,192] voxels
{
    __shared__ float2 tile[9][IN_D];   // [zi*3+yi][x], 9216 B
    float4* tile4 = (float4*)tile;

    const int blk = blockIdx.x;
    const int yk = blk & 63;
    const int zk = (blk >> 6) & 63;
    const int b  = blk >> 12;

    const int tid = threadIdx.x;       // 0..191

    // ---- Phase 1: cooperative float4 load of 9 input rows (576 float4) ----
    // thread handles float4 #(tid&63) of rows (tid>>6), (tid>>6)+3, (tid>>6)+6
    {
        const float4* in4 =
            (const float4*)(in + (size_t)b * (IN_D * IN_D * IN_D));
        const int lf4 = tid & 63;      // float4 index within a 128-voxel row
        const int yi  = tid >> 6;      // 0..2 (row-within-plane for this thread)
        const int y   = min(2 * yk + yi, IN_D - 1);
        #pragma unroll
        for (int zi = 0; zi < 3; zi++) {
            int z = min(2 * zk + zi, IN_D - 1);
            tile4[(zi * 3 + yi) * 64 + lf4] =
                __ldg(in4 + ((size_t)z * IN_D + y) * 64 + lf4);
        }
    }
    __syncthreads();

    // ---- Phase 2: per-thread x-lerp, then y/z lerp in registers ----
    const float c13 = 1.0f / 3.0f;
    const float c23 = 2.0f / 3.0f;

    const int k  = tid / 3;            // output micro-block index along x
    const int xo = tid - 3 * k;        // 0,1,2 within micro-block

    int xA, xB;
    float wA;
    if (xo == 0)      { xA = 2 * k;     xB = xA;                     wA = 1.0f; }
    else if (xo == 1) { xA = 2 * k;     xB = 2 * k + 1;              wA = c13;  }
    else              { xA = 2 * k + 1; xB = min(2 * k + 2, IN_D-1); wA = c23;  }
    const float wB = 1.0f - wA;

    float2 xl[9];                      // x-lerped, [zi*3+yi]
    #pragma unroll
    for (int r = 0; r < 9; r++) {
        float2 a = tile[r][xA];
        float2 c = tile[r][xB];
        xl[r] = lerp2(a, c, wA, wB);
    }

    // y-lerp: per z-plane, 3 input y -> 3 output y
    float2 yl[3][3];                   // [zi][yo]
    #pragma unroll
    for (int zi = 0; zi < 3; zi++) {
        float2 v0 = xl[3 * zi + 0];
        float2 v1 = xl[3 * zi + 1];
        float2 v2 = xl[3 * zi + 2];
        yl[zi][0] = v0;
        yl[zi][1] = lerp2(v0, v1, c13, c23);
        yl[zi][2] = lerp2(v1, v2, c23, c13);
    }

    // z-lerp + 27 coalesced stores (immediate offsets off one base)
    float2* obase = out +
        ((((size_t)b * OUT_D + 3 * zk) * OUT_D + 3 * yk) * OUT_D + tid);
    #pragma unroll
    for (int yo = 0; yo < 3; yo++) {
        float2 v0 = yl[0][yo];
        float2 v1 = yl[1][yo];
        float2 v2 = yl[2][yo];
        obase[(size_t)(0 * OUT_D + yo) * OUT_D] = v0;
        obase[(size_t)(1 * OUT_D + yo) * OUT_D] = lerp2(v0, v1, c13, c23);
        obase[(size_t)(2 * OUT_D + yo) * OUT_D] = lerp2(v1, v2, c23, c13);
    }
}

extern "C" void kernel_launch(void* const* d_in, const int* in_sizes, int n_in,
                              void* d_out, int out_size) {
    const float2* in = (const float2*)d_in[0];
    float2* out = (float2*)d_out;

    int blocks = 4 * 64 * 64;   // (b, zk, yk) = 16384
    resize_smem_f4_kernel<<<blocks, 192>>>(in, out);
}